// round 10
// baseline (speedup 1.0000x reference)
#include <cuda_runtime.h>
#include <cuda_fp16.h>

typedef unsigned long long ull;

#define BN 8192
#define TN 2048
#define MPC 4    // muscles per CTA

// Transposed excitation scratch: [T][B] layout for coalesced per-step loads.
__device__ float g_excT[(size_t)TN * BN];

__device__ __forceinline__ float tanha(float x) {
    float y; asm("tanh.approx.f32 %0, %1;" : "=f"(y) : "f"(x)); return y;
}
__device__ __forceinline__ ull pack2(float lo, float hi) {
    ull r; asm("mov.b64 %0, {%1, %2};" : "=l"(r) : "f"(lo), "f"(hi)); return r;
}
__device__ __forceinline__ void unpack2(ull v, float& lo, float& hi) {
    asm("mov.b64 {%0, %1}, %2;" : "=f"(lo), "=f"(hi) : "l"(v));
}
// Packed dual-FMA (f32x2) for the f32 layer-3 path.
__device__ __forceinline__ void ffma2(ull& d, ull a, ull b) {
    asm("fma.rn.f32x2 %0, %1, %2, %0;" : "+l"(d) : "l"(a), "l"(b));
}

// exc[B][T] -> g_excT[T][B]
__global__ void transpose_exc(const float* __restrict__ exc) {
    __shared__ float tile[32][33];
    int t0 = blockIdx.x * 32, b0 = blockIdx.y * 32;
    int tx = threadIdx.x, ty = threadIdx.y;
#pragma unroll
    for (int i = 0; i < 32; i += 8)
        tile[ty + i][tx] = exc[(size_t)(b0 + ty + i) * TN + t0 + tx];
    __syncthreads();
#pragma unroll
    for (int i = 0; i < 32; i += 8)
        g_excT[(size_t)(t0 + ty + i) * BN + b0 + tx] = tile[tx][ty + i];
}

// Weight-stationary fp16 layer-2, MPC=4 for 2x CTA count (6.9 warps/SMSP).
// CTA = 64 threads (2 warps), 4 muscles. Thread tid owns output neuron
// j = tid: the whole W2 column lives in 32 half2 registers; W1/b1/b2 are
// re-read from smem (broadcast LDS) to keep regs <= 73 so 14 CTAs/SM fit.
__global__ __launch_bounds__(64, 14) void ode_kernel(
    const float* __restrict__ init, const float* __restrict__ tspan,
    const float* __restrict__ W1, const float* __restrict__ b1,
    const float* __restrict__ W2, const float* __restrict__ b2,
    const float* __restrict__ W3, const float* __restrict__ b3,
    float* __restrict__ out)
{
    __shared__ __align__(16) __half h_s[MPC * 72];   // fp16 rows, 144B stride
    __shared__ __align__(16) float o_s[MPC * 72];    // layer-2 outputs (f32)
    __shared__ __align__(16) float x_s[MPC * 4];
    __shared__ __align__(16) float w1t[4][64];       // W1 as [j][in] quads
    __shared__ __align__(16) float sb1[64];
    __shared__ __align__(16) float sb2[64];
    __shared__ __align__(16) float w3t[3][68];       // transposed W3, padded
    __shared__ __align__(16) float sb3[4];

    const int tid  = threadIdx.x;
    const int lane = tid & 31;
    const int warp = tid >> 5;
    const int jg   = tid;                 // output-neuron index 0..63

    // one-time weight staging
    for (int i = tid; i < 192; i += 64) w3t[i % 3][i / 3] = W3[i];
    {   // w1t[j] = {W1[0][j], W1[1][j], W1[2][j], W1[3][j]}
        w1t[0][jg] = W1[jg];       w1t[1][jg] = W1[64 + jg];
        w1t[2][jg] = W1[128 + jg]; w1t[3][jg] = W1[192 + jg];
        sb1[jg] = b1[jg];
        sb2[jg] = b2[jg];
    }
    if (tid < 3) sb3[tid] = b3[tid];
    if (tid == 3) sb3[3] = 0.0f;

    // fp16 W2 column: pair i holds (W2[2i][j], W2[2i+1][j])
    __half2 w2h[32];
#pragma unroll
    for (int i = 0; i < 32; i++)
        w2h[i] = __floats2half2_rn(W2[(2 * i) * 64 + jg],
                                   W2[(2 * i + 1) * 64 + jg]);

    const bool owner = lane < 2;
    const int  mo = warp * 2 + lane;               // muscle owned (if owner)
    const int  bo = blockIdx.x * MPC + mo;

    float y0 = 0.f, y1 = 0.f, y2 = 0.f, ep = 0.f, tprev = 0.f;
    if (owner) {
        y0 = init[bo * 3 + 0];
        y1 = init[bo * 3 + 1];
        y2 = init[bo * 3 + 2];
        out[bo * 3 + 0] = y0; out[bo * 3 + 1] = y1; out[bo * 3 + 2] = y2;
        ep = g_excT[bo];                 // k1 at step 0 uses exc[:, 0]
        tprev = tspan[0];
        *(float4*)(x_s + mo * 4) = make_float4(y0, y1, y2, ep);
    }
    __syncthreads();

#pragma unroll 1
    for (int it = 0; it < TN - 1; it++) {
        float ec = 0.f, dt = 0.f, hd = 0.f;
        float a0 = y0, a1 = y1, a2 = y2;
        float s0 = 0.f, s1 = 0.f, s2 = 0.f;
        if (owner) {
            ec = g_excT[(size_t)it * BN + bo];     // exc[:, it] for k2/k3/k4
            float tnext = tspan[it + 1];
            dt = tnext - tprev;
            tprev = tnext;
            hd = 0.5f * dt;
        }

#pragma unroll 1
        for (int sg = 0; sg < 4; sg++) {
            // ---- slot 1: layer-1 (all threads) + physics (owner lanes) ----
            {
                float w10 = w1t[0][jg], w11 = w1t[1][jg],
                      w12 = w1t[2][jg], w13 = w1t[3][jg];
                float b1j = sb1[jg];
#pragma unroll
                for (int m = 0; m < MPC; m++) {
                    float4 x = *(const float4*)(x_s + m * 4);   // broadcast
                    float t = fmaf(x.x, w10,
                              fmaf(x.y, w11,
                              fmaf(x.z, w12,
                              fmaf(x.w, w13, b1j))));
                    h_s[m * 72 + jg] = __float2half(tanha(t));
                }
            }

            float k0 = 0.f, k1d = 0.f, k2d = 0.f;
            if (owner) {
                float e = (sg == 0) ? ep : ec;
                float lM   = fminf(fmaxf(a0, 0.0445f), 0.1424f);
                float act  = fminf(fmaxf(a1, 0.01f), 1.0f);
                float fat  = fminf(fmaxf(a2, 0.0f), 1.0f);
                float aeff = act * (1.0f - fat);
                // L0*sin(PENN0) = 0.089*sin(0.0873)
                float sinp = fminf(__fdividef(0.00775983457f, lM), 0.99f);
                float cosp = sqrtf(1.0f - sinp * sinp);
                // LMT_DEFAULT = 0.126 + 0.089*cos(0.0873)
                float lT   = 0.214661068f - lM * cosp;
                float epsT = (lT - 0.126f) * (1.0f / 0.126f);
                float fT   = (epsT > 0.0f) ? 0.2f * (__expf(35.0f * epsT) - 1.0f) : 0.0f;
                float lN   = lM * (1.0f / 0.089f);
                float ddv  = lN - 1.0f;
                float fL   = __expf(-ddv * ddv * (1.0f / 0.45f));
                float fPE  = (lN > 1.0f)
                           ? (__expf(ddv * (5.0f / 0.6f)) - 1.0f) * (1.0f / 147.4131591f)
                           : 0.0f;
                float fV   = __fdividef(__fdividef(fT, cosp) - fPE, aeff * fL + 0.001f);
                float vN   = fminf(fmaxf(__fdividef(fV - 1.0f, 1.0f + fabsf(fV) * 4.0f),
                                         -1.0f), 1.5f);
                k0   = 0.89f * vN;                        // VMAX*L0*vN
                float tau = (e > act) ? 0.01f * (0.5f + 1.5f * act)
                                      : __fdividef(0.04f, 0.5f + 1.5f * act);
                k1d  = __fdividef(e - act, tau);
                k2d  = 0.01f * aeff * (1.0f - fat) - 0.002f * (1.0f - aeff) * fat;
            }
            __syncthreads();

            // ---- slot 2: fp16 layer-2, 2 muscles in flight (4 acc chains) ----
#pragma unroll 1
            for (int m = 0; m < MPC; m += 2) {
                const uint4* hA = (const uint4*)(h_s + m * 72);
                const uint4* hB = (const uint4*)(h_s + (m + 1) * 72);
                __half2 aA0 = __floats2half2_rn(0.f, 0.f);
                __half2 aA1 = __floats2half2_rn(0.f, 0.f);
                __half2 aB0 = __floats2half2_rn(0.f, 0.f);
                __half2 aB1 = __floats2half2_rn(0.f, 0.f);
#pragma unroll
                for (int q = 0; q < 8; q++) {
                    uint4 qa = hA[q];                     // broadcast LDS.128
                    uint4 qb = hB[q];
                    const __half2* pa = (const __half2*)&qa;
                    const __half2* pb = (const __half2*)&qb;
                    aA0 = __hfma2(pa[0], w2h[q * 4 + 0], aA0);
                    aA1 = __hfma2(pa[1], w2h[q * 4 + 1], aA1);
                    aB0 = __hfma2(pb[0], w2h[q * 4 + 0], aB0);
                    aB1 = __hfma2(pb[1], w2h[q * 4 + 1], aB1);
                    aA0 = __hfma2(pa[2], w2h[q * 4 + 2], aA0);
                    aA1 = __hfma2(pa[3], w2h[q * 4 + 3], aA1);
                    aB0 = __hfma2(pb[2], w2h[q * 4 + 2], aB0);
                    aB1 = __hfma2(pb[3], w2h[q * 4 + 3], aB1);
                }
                float b2j = sb2[jg];
                float2 fa0 = __half22float2(aA0);
                float2 fa1 = __half22float2(aA1);
                o_s[m * 72 + jg] =
                    tanha(((fa0.x + fa0.y) + (fa1.x + fa1.y)) + b2j);
                float2 fb0 = __half22float2(aB0);
                float2 fb1 = __half22float2(aB1);
                o_s[(m + 1) * 72 + jg] =
                    tanha(((fb0.x + fb0.y) + (fb1.x + fb1.y)) + b2j);
            }
            __syncthreads();

            // ---- slot 3: layer-3 + RK4 (owner lanes) ----
            if (owner) {
                const ulonglong2* orow = (const ulonglong2*)(o_s + mo * 72);
                const ulonglong2* w3r0 = (const ulonglong2*)(w3t[0]);
                const ulonglong2* w3r1 = (const ulonglong2*)(w3t[1]);
                const ulonglong2* w3r2 = (const ulonglong2*)(w3t[2]);
                ull P0 = 0, P1 = 0, P2 = 0;
#pragma unroll
                for (int q = 0; q < 16; q++) {
                    ulonglong2 oq = orow[q];
                    ulonglong2 wq0 = w3r0[q], wq1 = w3r1[q], wq2 = w3r2[q];
                    ffma2(P0, oq.x, wq0.x); ffma2(P0, oq.y, wq0.y);
                    ffma2(P1, oq.x, wq1.x); ffma2(P1, oq.y, wq1.y);
                    ffma2(P2, oq.x, wq2.x); ffma2(P2, oq.y, wq2.y);
                }
                float p0a, p0b, p1a, p1b, p2a, p2b;
                unpack2(P0, p0a, p0b);
                unpack2(P1, p1a, p1b);
                unpack2(P2, p2a, p2b);
                float p0 = p0a + p0b, p1 = p1a + p1b, p2 = p2a + p2b;

                k0  += 0.2f * (0.1f * tanha(p0 + sb3[0]));
                k1d += 0.2f * (0.1f * tanha(p1 + sb3[1]));
                k2d += 0.2f * (0.1f * tanha(p2 + sb3[2]));

                float wgt = (sg == 1 || sg == 2) ? 2.0f : 1.0f;
                s0 = fmaf(wgt, k0,  s0);
                s1 = fmaf(wgt, k1d, s1);
                s2 = fmaf(wgt, k2d, s2);

                if (sg < 3) {
                    float st = (sg < 2) ? hd : dt;
                    a0 = y0 + st * k0;
                    a1 = y1 + st * k1d;
                    a2 = y2 + st * k2d;
                    *(float4*)(x_s + mo * 4) = make_float4(a0, a1, a2, ec);
                } else {
                    float w6 = dt * (1.0f / 6.0f);
                    y0 += w6 * s0; y1 += w6 * s1; y2 += w6 * s2;
                    size_t o = (size_t)(it + 1) * (BN * 3) + (size_t)bo * 3;
                    out[o] = y0; out[o + 1] = y1; out[o + 2] = y2;
                    // next step's k1 excitation = this step's ec
                    *(float4*)(x_s + mo * 4) = make_float4(y0, y1, y2, ec);
                }
            }
            __syncthreads();
        }
        if (owner) ep = ec;
    }
}

extern "C" void kernel_launch(void* const* d_in, const int* in_sizes, int n_in,
                              void* d_out, int out_size) {
    const float* init = (const float*)d_in[0];
    const float* exc  = (const float*)d_in[1];
    const float* ts   = (const float*)d_in[2];
    const float* W1   = (const float*)d_in[3];
    const float* b1   = (const float*)d_in[4];
    const float* W2   = (const float*)d_in[5];
    const float* b2   = (const float*)d_in[6];
    const float* W3   = (const float*)d_in[7];
    const float* b3   = (const float*)d_in[8];
    float* out = (float*)d_out;

    dim3 tb(32, 8);
    dim3 tg(TN / 32, BN / 32);
    transpose_exc<<<tg, tb>>>(exc);
    ode_kernel<<<BN / MPC, 64>>>(init, ts, W1, b1, W2, b2, W3, b3, out);
}

// round 11
// speedup vs baseline: 2.0907x; 2.0907x over previous
#include <cuda_runtime.h>
#include <cuda_fp16.h>

typedef unsigned int uint32;

#define BN 8192
#define TN 2048
#define MPC 8    // muscles per CTA (rows 0..7 of the 16-row MMA tile)

// Transposed excitation scratch: [T][B] layout for coalesced per-step loads.
__device__ float g_excT[(size_t)TN * BN];

__device__ __forceinline__ float tanha(float x) {
    float y; asm("tanh.approx.f32 %0, %1;" : "=f"(y) : "f"(x)); return y;
}
__device__ __forceinline__ uint32 packh2(float lo, float hi) {
    __half2 h = __floats2half2_rn(lo, hi);
    return *(uint32*)&h;
}

// exc[B][T] -> g_excT[T][B]
__global__ void transpose_exc(const float* __restrict__ exc) {
    __shared__ float tile[32][33];
    int t0 = blockIdx.x * 32, b0 = blockIdx.y * 32;
    int tx = threadIdx.x, ty = threadIdx.y;
#pragma unroll
    for (int i = 0; i < 32; i += 8)
        tile[ty + i][tx] = exc[(size_t)(b0 + ty + i) * TN + t0 + tx];
    __syncthreads();
#pragma unroll
    for (int i = 0; i < 32; i += 8)
        g_excT[(size_t)(t0 + ty + i) * BN + b0 + tx] = tile[tx][ty + i];
}

// Tensor-core formulation. CTA = 64 threads (2 warps), 8 muscles.
// Layer-2 is one batched [16x64]x[64x64] fp16 MMA (f32 accum): h rows =
// muscles (rows 8-15 zero), W2 fragments live permanently in registers
// (each warp owns a 32-wide N-half). Layer-3 folds into the MMA epilogue:
// each lane holds 8 layer-2 outputs of ONE muscle, multiplies by its
// preloaded W3 rows, quad-shuffle reduces, and stages 3 partials.
// Physics / RK4 stay on lanes 0..3 of each warp as before.
__global__ __launch_bounds__(64, 7) void ode_kernel(
    const float* __restrict__ init, const float* __restrict__ tspan,
    const float* __restrict__ W1, const float* __restrict__ b1,
    const float* __restrict__ W2, const float* __restrict__ b2,
    const float* __restrict__ W3, const float* __restrict__ b3,
    float* __restrict__ out)
{
    __shared__ __align__(128) __half h_s[16 * 64];  // A tile, 128B row stride
    __shared__ __align__(16) float pp[16 * 4];      // layer-3 partials [w*8+m]
    __shared__ __align__(16) float x_s[MPC * 4];
    __shared__ __align__(16) float sb3[4];

    const int tid  = threadIdx.x;
    const int lane = tid & 31;
    const int warp = tid >> 5;
    const int jg   = tid;                 // layer-1 output-neuron index

    // zero the A tile once (rows 8-15 stay zero forever)
    for (int i = tid; i < 16 * 64; i += 64) h_s[i] = __float2half(0.0f);
    if (tid < 3) sb3[tid] = b3[tid];
    if (tid == 3) sb3[3] = 0.0f;

    // layer-1 column for this thread
    const float w10 = W1[jg], w11 = W1[64 + jg],
                w12 = W1[128 + jg], w13 = W1[192 + jg];
    const float b1j = b1[jg];

    // W2 B-fragments (m16n8k16, col layout): n = warp*32 + nt*8 + lane/4,
    // k = ck*16 + (lane%4)*2 (+1, +8, +9). 16 fragments x 2 regs.
    uint32 bfrag[4][4][2];
#pragma unroll
    for (int nt = 0; nt < 4; nt++) {
#pragma unroll
        for (int ck = 0; ck < 4; ck++) {
            int n  = warp * 32 + nt * 8 + (lane >> 2);
            int k0 = ck * 16 + (lane & 3) * 2;
            bfrag[nt][ck][0] = packh2(W2[k0 * 64 + n], W2[(k0 + 1) * 64 + n]);
            bfrag[nt][ck][1] = packh2(W2[(k0 + 8) * 64 + n], W2[(k0 + 9) * 64 + n]);
        }
    }
    // layer-3 weights + b2 for this lane's 8 output columns:
    // j0 = warp*32 + nt*8 + (lane%4)*2, j1 = j0+1  (C-fragment cols)
    float w3a[4][3], w3b[4][3];
    float2 b2v[4];
#pragma unroll
    for (int nt = 0; nt < 4; nt++) {
        int j0 = warp * 32 + nt * 8 + (lane & 3) * 2;
#pragma unroll
        for (int c = 0; c < 3; c++) {
            w3a[nt][c] = W3[j0 * 3 + c];
            w3b[nt][c] = W3[(j0 + 1) * 3 + c];
        }
        b2v[nt] = make_float2(b2[j0], b2[j0 + 1]);
    }

    const uint32 hbase = (uint32)__cvta_generic_to_shared(h_s);
    const uint32 a_addr = hbase + (lane & 15) * 128 + (lane >> 4) * 16;

    const bool owner = lane < 4;
    const int  mo = warp * 4 + lane;               // muscle owned (if owner)
    const int  bo = blockIdx.x * MPC + mo;

    float y0 = 0.f, y1 = 0.f, y2 = 0.f, ep = 0.f, tprev = 0.f;
    if (owner) {
        y0 = init[bo * 3 + 0];
        y1 = init[bo * 3 + 1];
        y2 = init[bo * 3 + 2];
        out[bo * 3 + 0] = y0; out[bo * 3 + 1] = y1; out[bo * 3 + 2] = y2;
        ep = g_excT[bo];                 // k1 at step 0 uses exc[:, 0]
        tprev = tspan[0];
        *(float4*)(x_s + mo * 4) = make_float4(y0, y1, y2, ep);
    }
    __syncthreads();

#pragma unroll 1
    for (int it = 0; it < TN - 1; it++) {
        float ec = 0.f, dt = 0.f, hd = 0.f;
        float a0s = y0, a1s = y1, a2s = y2;
        float s0 = 0.f, s1 = 0.f, s2 = 0.f;
        if (owner) {
            ec = g_excT[(size_t)it * BN + bo];     // exc[:, it] for k2/k3/k4
            float tnext = tspan[it + 1];
            dt = tnext - tprev;
            tprev = tnext;
            hd = 0.5f * dt;
        }

#pragma unroll 1
        for (int sg = 0; sg < 4; sg++) {
            // ---- slot 1: layer-1 (all threads) + physics (owner lanes) ----
#pragma unroll
            for (int m = 0; m < MPC; m++) {
                float4 x = *(const float4*)(x_s + m * 4);   // broadcast
                float t = fmaf(x.x, w10,
                          fmaf(x.y, w11,
                          fmaf(x.z, w12,
                          fmaf(x.w, w13, b1j))));
                h_s[m * 64 + jg] = __float2half(tanha(t));
            }

            float k0 = 0.f, k1d = 0.f, k2d = 0.f;
            if (owner) {
                float e = (sg == 0) ? ep : ec;
                float lM   = fminf(fmaxf(a0s, 0.0445f), 0.1424f);
                float act  = fminf(fmaxf(a1s, 0.01f), 1.0f);
                float fat  = fminf(fmaxf(a2s, 0.0f), 1.0f);
                float aeff = act * (1.0f - fat);
                // L0*sin(PENN0) = 0.089*sin(0.0873)
                float sinp = fminf(__fdividef(0.00775983457f, lM), 0.99f);
                float cosp = sqrtf(1.0f - sinp * sinp);
                // LMT_DEFAULT = 0.126 + 0.089*cos(0.0873)
                float lT   = 0.214661068f - lM * cosp;
                float epsT = (lT - 0.126f) * (1.0f / 0.126f);
                float fT   = (epsT > 0.0f) ? 0.2f * (__expf(35.0f * epsT) - 1.0f) : 0.0f;
                float lN   = lM * (1.0f / 0.089f);
                float ddv  = lN - 1.0f;
                float fL   = __expf(-ddv * ddv * (1.0f / 0.45f));
                float fPE  = (lN > 1.0f)
                           ? (__expf(ddv * (5.0f / 0.6f)) - 1.0f) * (1.0f / 147.4131591f)
                           : 0.0f;
                float fV   = __fdividef(__fdividef(fT, cosp) - fPE, aeff * fL + 0.001f);
                float vN   = fminf(fmaxf(__fdividef(fV - 1.0f, 1.0f + fabsf(fV) * 4.0f),
                                         -1.0f), 1.5f);
                k0   = 0.89f * vN;                        // VMAX*L0*vN
                float tau = (e > act) ? 0.01f * (0.5f + 1.5f * act)
                                      : __fdividef(0.04f, 0.5f + 1.5f * act);
                k1d  = __fdividef(e - act, tau);
                k2d  = 0.01f * aeff * (1.0f - fat) - 0.002f * (1.0f - aeff) * fat;
            }
            __syncthreads();

            // ---- slot 2: layer-2 via HMMA + fused layer-3 epilogue ----
            float c[4][4];
#pragma unroll
            for (int nt = 0; nt < 4; nt++)
                c[nt][0] = c[nt][1] = c[nt][2] = c[nt][3] = 0.0f;
#pragma unroll
            for (int ck = 0; ck < 4; ck++) {
                uint32 af0, af1, af2, af3;
                asm volatile(
                    "ldmatrix.sync.aligned.m8n8.x4.shared.b16 {%0,%1,%2,%3}, [%4];"
                    : "=r"(af0), "=r"(af1), "=r"(af2), "=r"(af3)
                    : "r"(a_addr + ck * 32));
#pragma unroll
                for (int nt = 0; nt < 4; nt++) {
                    asm volatile(
                        "mma.sync.aligned.m16n8k16.row.col.f32.f16.f16.f32 "
                        "{%0,%1,%2,%3}, {%4,%5,%6,%7}, {%8,%9}, {%0,%1,%2,%3};"
                        : "+f"(c[nt][0]), "+f"(c[nt][1]),
                          "+f"(c[nt][2]), "+f"(c[nt][3])
                        : "r"(af0), "r"(af1), "r"(af2), "r"(af3),
                          "r"(bfrag[nt][ck][0]), "r"(bfrag[nt][ck][1]));
                }
            }
            // epilogue: this lane holds o-pre of muscle (lane>>2) at 8 cols
            float p0 = 0.f, p1 = 0.f, p2 = 0.f;
#pragma unroll
            for (int nt = 0; nt < 4; nt++) {
                float o0 = tanha(c[nt][0] + b2v[nt].x);
                float o1 = tanha(c[nt][1] + b2v[nt].y);
                p0 = fmaf(o0, w3a[nt][0], fmaf(o1, w3b[nt][0], p0));
                p1 = fmaf(o0, w3a[nt][1], fmaf(o1, w3b[nt][1], p1));
                p2 = fmaf(o0, w3a[nt][2], fmaf(o1, w3b[nt][2], p2));
            }
            // reduce across the 4 lanes sharing this muscle
            p0 += __shfl_xor_sync(0xffffffffu, p0, 1);
            p0 += __shfl_xor_sync(0xffffffffu, p0, 2);
            p1 += __shfl_xor_sync(0xffffffffu, p1, 1);
            p1 += __shfl_xor_sync(0xffffffffu, p1, 2);
            p2 += __shfl_xor_sync(0xffffffffu, p2, 1);
            p2 += __shfl_xor_sync(0xffffffffu, p2, 2);
            if ((lane & 3) == 0)
                *(float4*)(pp + (warp * 8 + (lane >> 2)) * 4) =
                    make_float4(p0, p1, p2, 0.0f);
            __syncthreads();

            // ---- slot 3: combine + RK4 (owner lanes) ----
            if (owner) {
                float4 q0 = *(const float4*)(pp + mo * 4);
                float4 q1 = *(const float4*)(pp + (8 + mo) * 4);
                float pa = q0.x + q1.x;
                float pb = q0.y + q1.y;
                float pc = q0.z + q1.z;

                k0  += 0.2f * (0.1f * tanha(pa + sb3[0]));
                k1d += 0.2f * (0.1f * tanha(pb + sb3[1]));
                k2d += 0.2f * (0.1f * tanha(pc + sb3[2]));

                float wgt = (sg == 1 || sg == 2) ? 2.0f : 1.0f;
                s0 = fmaf(wgt, k0,  s0);
                s1 = fmaf(wgt, k1d, s1);
                s2 = fmaf(wgt, k2d, s2);

                if (sg < 3) {
                    float st = (sg < 2) ? hd : dt;
                    a0s = y0 + st * k0;
                    a1s = y1 + st * k1d;
                    a2s = y2 + st * k2d;
                    *(float4*)(x_s + mo * 4) = make_float4(a0s, a1s, a2s, ec);
                } else {
                    float w6 = dt * (1.0f / 6.0f);
                    y0 += w6 * s0; y1 += w6 * s1; y2 += w6 * s2;
                    size_t o = (size_t)(it + 1) * (BN * 3) + (size_t)bo * 3;
                    out[o] = y0; out[o + 1] = y1; out[o + 2] = y2;
                    // next step's k1 excitation = this step's ec
                    *(float4*)(x_s + mo * 4) = make_float4(y0, y1, y2, ec);
                }
            }
            __syncthreads();
        }
        if (owner) ep = ec;
    }
}

extern "C" void kernel_launch(void* const* d_in, const int* in_sizes, int n_in,
                              void* d_out, int out_size) {
    const float* init = (const float*)d_in[0];
    const float* exc  = (const float*)d_in[1];
    const float* ts   = (const float*)d_in[2];
    const float* W1   = (const float*)d_in[3];
    const float* b1   = (const float*)d_in[4];
    const float* W2   = (const float*)d_in[5];
    const float* b2   = (const float*)d_in[6];
    const float* W3   = (const float*)d_in[7];
    const float* b3   = (const float*)d_in[8];
    float* out = (float*)d_out;

    dim3 tb(32, 8);
    dim3 tg(TN / 32, BN / 32);
    transpose_exc<<<tg, tb>>>(exc);
    ode_kernel<<<BN / MPC, 64>>>(init, ts, W1, b1, W2, b2, W3, b3, out);
}